// round 9
// baseline (speedup 1.0000x reference)
#include <cuda_runtime.h>
#include <math.h>
#include <stdint.h>

#define Bn 16384
#define En 256
#define Vn 128
#define Tn 16
#define G3 768

#define OUT_UTT  ((size_t)Bn * Tn * Vn)
#define OUT_NOFF (OUT_UTT)
#define OUT_ROFF (OUT_UTT + Bn)

typedef unsigned long long ull;

// ---------------- packed f32x2 helpers ----------------
__device__ __forceinline__ ull pack2(float x, float y) {
    ull r; asm("mov.b64 %0, {%1, %2};" : "=l"(r) : "f"(x), "f"(y)); return r;
}
__device__ __forceinline__ void unpack2(ull v, float& x, float& y) {
    asm("mov.b64 {%0, %1}, %2;" : "=f"(x), "=f"(y) : "l"(v));
}
__device__ __forceinline__ void fma2(ull& c, ull a, ull b) {
    asm("fma.rn.f32x2 %0, %1, %2, %3;" : "=l"(c) : "l"(a), "l"(b), "l"(c));
}

// ---------------- device scratch ----------------
__device__ float g_h [2][Bn * En];
__device__ float g_he[2][Bn * En];
__device__ float g_Mdec[Vn * G3];
__device__ float g_cdec[G3];
__device__ float g_Menc[Vn * G3];
__device__ float g_cenc[G3];
__device__ int   g_tok [Bn];
__device__ int   g_toks[Tn * Bn];
__device__ int   g_N   [Bn];
__device__ unsigned char g_alive[Bn];

// ---------------- init ----------------
__global__ void k_init(const float* __restrict__ x) {
    int i = blockIdx.x * blockDim.x + threadIdx.x;
    if (i < Bn * En) { g_h[0][i] = x[i]; }
    if (i < Bn)      { g_tok[i] = -1; g_alive[i] = 1; g_N[i] = Tn; }
}

// ---------------- k_prep: M = (Wih @ Wd2e)^T, cvec = Wih@bd2e + bih ----------------
__global__ void k_prep(const float* __restrict__ Wih, const float* __restrict__ Wd2e,
                       const float* __restrict__ bd2e, const float* __restrict__ bih,
                       float* __restrict__ M, float* __restrict__ cvec) {
    __shared__ float sw[En];
    __shared__ float sb[En];
    const int v  = blockIdx.x;
    const int j0 = blockIdx.y * 64;
    for (int e = threadIdx.x; e < En; e += 256) {
        sw[e] = Wd2e[e * Vn + v];
        if (v == 0) sb[e] = bd2e[e];
    }
    __syncthreads();
    const int warp = threadIdx.x >> 5, lane = threadIdx.x & 31;
#pragma unroll
    for (int jj = 0; jj < 8; jj++) {
        const int j = j0 + warp * 8 + jj;
        const float* wr = Wih + (size_t)j * En;
        float s = 0.f, c = 0.f;
#pragma unroll
        for (int e = lane; e < En; e += 32) {
            float w = wr[e];
            s += w * sw[e];
            if (v == 0) c += w * sb[e];
        }
#pragma unroll
        for (int o = 16; o; o >>= 1) {
            s += __shfl_xor_sync(0xffffffffu, s, o);
            if (v == 0) c += __shfl_xor_sync(0xffffffffu, c, o);
        }
        if (lane == 0) {
            M[v * G3 + j] = s;
            if (v == 0) cvec[j] = bih[j] + c;
        }
    }
}

__device__ __forceinline__ float sigm(float x) { return 1.f / (1.f + expf(-x)); }

// ---------------- k_enc0: encoder step 0 (hin == 0 exactly) ----------------
__global__ void k_enc0(float* __restrict__ hout,
                       const float* __restrict__ M, const float* __restrict__ cvec,
                       const float* __restrict__ bhh, const int* __restrict__ tokv) {
    int i = blockIdx.x * blockDim.x + threadIdx.x;
    if (i >= Bn * En) return;
    int b = i >> 8;
    int j = i & 255;
    int tk = tokv[b];
    float mr = 0.f, mz = 0.f, mn = 0.f;
    if (tk >= 0) {
        const float* Mr = M + (size_t)tk * G3;
        mr = Mr[j]; mz = Mr[256 + j]; mn = Mr[512 + j];
    }
    float ir = mr + cvec[j],        hr = 0.f + bhh[j];
    float iz = mz + cvec[256 + j],  hz = 0.f + bhh[256 + j];
    float in_= mn + cvec[512 + j],  hn = 0.f + bhh[512 + j];
    float r = sigm(ir + hr);
    float z = sigm(iz + hz);
    float n = tanhf(in_ + r * hn);
    hout[i] = (1.f - z) * n + z * 0.f;
}

// ---------------- fused gates GEMM (f32x2, pre-duplicated A) + GRU, dual-dispatch ----------------
__global__ __launch_bounds__(256, 2) void k_gates2(
    const float* hinA, float* houtA, const float* WhhA, const float* bhhA,
    const float* MA, const float* cvA, const int* tokA,
    const float* hinB, float* houtB, const float* WhhB, const float* bhhB,
    const float* MB, const float* cvB, const int* tokB)
{
    const int zb = blockIdx.z;
    const float* __restrict__ hin  = zb ? hinB  : hinA;
    float*       __restrict__ hout = zb ? houtB : houtA;
    const float* __restrict__ Whh  = zb ? WhhB  : WhhA;
    const float* __restrict__ bhh  = zb ? bhhB  : bhhA;
    const float* __restrict__ M    = zb ? MB    : MA;
    const float* __restrict__ cvec = zb ? cvB   : cvA;
    const int*   __restrict__ tok  = zb ? tokB  : tokA;

    __shared__ ull   As2[2][16][66];     // (a,a) pairs, 8B each
    __shared__ float Ws[2][16][196];
    const int t  = threadIdx.x;
    const int r0 = blockIdx.x * 64;
    const int j0 = blockIdx.y * 64;
    const int ty = t >> 4, tx = t & 15;

    const int lr  = t >> 2;
    const int lkq = (t & 3) * 4;
    const float* Ag  = hin + (size_t)(r0 + lr) * En + lkq;
    const float* Wg0 = Whh + (size_t)(0 * En + j0 + lr) * En + lkq;
    const float* Wg1 = Whh + (size_t)(1 * En + j0 + lr) * En + lkq;
    const float* Wg2 = Whh + (size_t)(2 * En + j0 + lr) * En + lkq;

    float4 av = *(const float4*)Ag;
    float4 w0 = *(const float4*)Wg0;
    float4 w1 = *(const float4*)Wg1;
    float4 w2 = *(const float4*)Wg2;

    ull acc2[3][4][2];
#pragma unroll
    for (int g = 0; g < 3; g++)
#pragma unroll
        for (int i = 0; i < 4; i++) { acc2[g][i][0] = 0ull; acc2[g][i][1] = 0ull; }

    As2[0][lkq+0][lr] = pack2(av.x, av.x); As2[0][lkq+1][lr] = pack2(av.y, av.y);
    As2[0][lkq+2][lr] = pack2(av.z, av.z); As2[0][lkq+3][lr] = pack2(av.w, av.w);
    Ws[0][lkq+0][lr      ] = w0.x; Ws[0][lkq+1][lr      ] = w0.y; Ws[0][lkq+2][lr      ] = w0.z; Ws[0][lkq+3][lr      ] = w0.w;
    Ws[0][lkq+0][64  + lr] = w1.x; Ws[0][lkq+1][64  + lr] = w1.y; Ws[0][lkq+2][64  + lr] = w1.z; Ws[0][lkq+3][64  + lr] = w1.w;
    Ws[0][lkq+0][128 + lr] = w2.x; Ws[0][lkq+1][128 + lr] = w2.y; Ws[0][lkq+2][128 + lr] = w2.z; Ws[0][lkq+3][128 + lr] = w2.w;
    __syncthreads();

    for (int kt = 0; kt < 16; kt++) {
        const int buf = kt & 1;
        if (kt < 15) {
            av = *(const float4*)(Ag  + (kt + 1) * 16);
            w0 = *(const float4*)(Wg0 + (kt + 1) * 16);
            w1 = *(const float4*)(Wg1 + (kt + 1) * 16);
            w2 = *(const float4*)(Wg2 + (kt + 1) * 16);
        }
#pragma unroll
        for (int k = 0; k < 16; k++) {
            const ull* arow_ = &As2[buf][k][ty * 4];
            ull ap[4];
            ap[0] = arow_[0]; ap[1] = arow_[1]; ap[2] = arow_[2]; ap[3] = arow_[3];
            ull bp[3][2];
#pragma unroll
            for (int g = 0; g < 3; g++) {
                ulonglong2 bv = *(const ulonglong2*)&Ws[buf][k][g * 64 + tx * 4];
                bp[g][0] = bv.x; bp[g][1] = bv.y;
            }
#pragma unroll
            for (int i = 0; i < 4; i++)
#pragma unroll
                for (int g = 0; g < 3; g++) {
                    fma2(acc2[g][i][0], ap[i], bp[g][0]);
                    fma2(acc2[g][i][1], ap[i], bp[g][1]);
                }
        }
        if (kt < 15) {
            const int nb = buf ^ 1;
            As2[nb][lkq+0][lr] = pack2(av.x, av.x); As2[nb][lkq+1][lr] = pack2(av.y, av.y);
            As2[nb][lkq+2][lr] = pack2(av.z, av.z); As2[nb][lkq+3][lr] = pack2(av.w, av.w);
            Ws[nb][lkq+0][lr      ] = w0.x; Ws[nb][lkq+1][lr      ] = w0.y; Ws[nb][lkq+2][lr      ] = w0.z; Ws[nb][lkq+3][lr      ] = w0.w;
            Ws[nb][lkq+0][64  + lr] = w1.x; Ws[nb][lkq+1][64  + lr] = w1.y; Ws[nb][lkq+2][64  + lr] = w1.z; Ws[nb][lkq+3][64  + lr] = w1.w;
            Ws[nb][lkq+0][128 + lr] = w2.x; Ws[nb][lkq+1][128 + lr] = w2.y; Ws[nb][lkq+2][128 + lr] = w2.z; Ws[nb][lkq+3][128 + lr] = w2.w;
            __syncthreads();
        }
    }

    float cv[3][4], bh[3][4];
#pragma unroll
    for (int g = 0; g < 3; g++) {
        float4 cf = *(const float4*)(cvec + g * En + j0 + tx * 4);
        cv[g][0]=cf.x; cv[g][1]=cf.y; cv[g][2]=cf.z; cv[g][3]=cf.w;
        float4 bf = *(const float4*)(bhh + g * En + j0 + tx * 4);
        bh[g][0]=bf.x; bh[g][1]=bf.y; bh[g][2]=bf.z; bh[g][3]=bf.w;
    }
#pragma unroll
    for (int i = 0; i < 4; i++) {
        const int rr = r0 + ty * 4 + i;
        const int tk = tok[rr];
        float m[3][4];
        if (tk >= 0) {
            const float* Mr = M + (size_t)tk * G3 + j0 + tx * 4;
#pragma unroll
            for (int g = 0; g < 3; g++) {
                float4 mf = *(const float4*)(Mr + g * En);
                m[g][0]=mf.x; m[g][1]=mf.y; m[g][2]=mf.z; m[g][3]=mf.w;
            }
        } else {
#pragma unroll
            for (int g = 0; g < 3; g++)
#pragma unroll
                for (int c = 0; c < 4; c++) m[g][c] = 0.f;
        }
        float acc[3][4];
#pragma unroll
        for (int g = 0; g < 3; g++) {
            unpack2(acc2[g][i][0], acc[g][0], acc[g][1]);
            unpack2(acc2[g][i][1], acc[g][2], acc[g][3]);
        }
        float4 hof = *(const float4*)(hin + (size_t)rr * En + j0 + tx * 4);
        float hold[4] = {hof.x, hof.y, hof.z, hof.w};
        float hnew[4];
#pragma unroll
        for (int c = 0; c < 4; c++) {
            float ir = m[0][c] + cv[0][c], hr = acc[0][c] + bh[0][c];
            float iz = m[1][c] + cv[1][c], hz = acc[1][c] + bh[1][c];
            float in_= m[2][c] + cv[2][c], hn = acc[2][c] + bh[2][c];
            float r = sigm(ir + hr);
            float z = sigm(iz + hz);
            float n = tanhf(in_ + r * hn);
            hnew[c] = (1.f - z) * n + z * hold[c];
        }
        *(float4*)(hout + (size_t)rr * En + j0 + tx * 4) = make_float4(hnew[0], hnew[1], hnew[2], hnew[3]);
    }
}

// ---------------- fused logits GEMM (f32x2, pre-duplicated A) + gumbel + argmax ----------------
__global__ __launch_bounds__(256, 2) void k_logits(
    const float* __restrict__ hin, const float* __restrict__ We2d,
    const float* __restrict__ be2d, const float* __restrict__ unif,
    float* __restrict__ out, int t)
{
    __shared__ ull   As2[2][16][66];
    __shared__ float Ws[2][16][132];
    __shared__ float sVal[64][17];
    __shared__ int   sIdx[64][17];
    __shared__ int   sBtok[64];
    const int tid = threadIdx.x;
    const int r0 = blockIdx.x * 64;
    const int ty = tid >> 4, tx = tid & 15;

    const int lr  = tid >> 2;
    const int lkq = (tid & 3) * 4;
    const float* Ag = hin + (size_t)(r0 + lr) * En + lkq;
    const int wn  = tid >> 1;
    const int wkq = (tid & 1) * 8;
    const float* Wg = We2d + (size_t)wn * En + wkq;

    float4 av = *(const float4*)Ag;
    float4 w0 = *(const float4*)Wg;
    float4 w1 = *(const float4*)(Wg + 4);

    ull acc2[4][4];
#pragma unroll
    for (int i = 0; i < 4; i++)
#pragma unroll
        for (int p = 0; p < 4; p++) acc2[i][p] = 0ull;

    As2[0][lkq+0][lr] = pack2(av.x, av.x); As2[0][lkq+1][lr] = pack2(av.y, av.y);
    As2[0][lkq+2][lr] = pack2(av.z, av.z); As2[0][lkq+3][lr] = pack2(av.w, av.w);
    Ws[0][wkq+0][wn] = w0.x; Ws[0][wkq+1][wn] = w0.y; Ws[0][wkq+2][wn] = w0.z; Ws[0][wkq+3][wn] = w0.w;
    Ws[0][wkq+4][wn] = w1.x; Ws[0][wkq+5][wn] = w1.y; Ws[0][wkq+6][wn] = w1.z; Ws[0][wkq+7][wn] = w1.w;
    __syncthreads();

    for (int kt = 0; kt < 16; kt++) {
        const int buf = kt & 1;
        if (kt < 15) {
            av = *(const float4*)(Ag + (kt + 1) * 16);
            w0 = *(const float4*)(Wg + (kt + 1) * 16);
            w1 = *(const float4*)(Wg + (kt + 1) * 16 + 4);
        }
#pragma unroll
        for (int k = 0; k < 16; k++) {
            const ull* arow_ = &As2[buf][k][ty * 4];
            ull ap[4];
            ap[0] = arow_[0]; ap[1] = arow_[1]; ap[2] = arow_[2]; ap[3] = arow_[3];
            ull bp[4];
            {
                ulonglong2 b0 = *(const ulonglong2*)&Ws[buf][k][     tx * 4];
                ulonglong2 b1 = *(const ulonglong2*)&Ws[buf][k][64 + tx * 4];
                bp[0] = b0.x; bp[1] = b0.y; bp[2] = b1.x; bp[3] = b1.y;
            }
#pragma unroll
            for (int i = 0; i < 4; i++)
#pragma unroll
                for (int p = 0; p < 4; p++) fma2(acc2[i][p], ap[i], bp[p]);
        }
        if (kt < 15) {
            const int nb = buf ^ 1;
            As2[nb][lkq+0][lr] = pack2(av.x, av.x); As2[nb][lkq+1][lr] = pack2(av.y, av.y);
            As2[nb][lkq+2][lr] = pack2(av.z, av.z); As2[nb][lkq+3][lr] = pack2(av.w, av.w);
            Ws[nb][wkq+0][wn] = w0.x; Ws[nb][wkq+1][wn] = w0.y; Ws[nb][wkq+2][wn] = w0.z; Ws[nb][wkq+3][wn] = w0.w;
            Ws[nb][wkq+4][wn] = w1.x; Ws[nb][wkq+5][wn] = w1.y; Ws[nb][wkq+6][wn] = w1.z; Ws[nb][wkq+7][wn] = w1.w;
            __syncthreads();
        }
    }

    float be[8];
    {
        float4 b0 = *(const float4*)(be2d +      tx * 4);
        float4 b1 = *(const float4*)(be2d + 64 + tx * 4);
        be[0]=b0.x; be[1]=b0.y; be[2]=b0.z; be[3]=b0.w;
        be[4]=b1.x; be[5]=b1.y; be[6]=b1.z; be[7]=b1.w;
    }
#pragma unroll
    for (int i = 0; i < 4; i++) {
        const int rr = r0 + ty * 4 + i;
        const float* urow = unif + ((size_t)t * Bn + rr) * Vn;
        float acc[8];
        unpack2(acc2[i][0], acc[0], acc[1]);
        unpack2(acc2[i][1], acc[2], acc[3]);
        unpack2(acc2[i][2], acc[4], acc[5]);
        unpack2(acc2[i][3], acc[6], acc[7]);
        float best = -INFINITY; int bidx = Vn;
#pragma unroll
        for (int c = 0; c < 8; c++) {
            const int col = (c < 4) ? (tx * 4 + c) : (64 + tx * 4 + (c - 4));
            float u = urow[col];
            float g = -logf(-logf(u + 1e-10f) + 1e-10f);
            float v = acc[c] + be[c] + g;
            if (v > best || (v == best && col < bidx)) { best = v; bidx = col; }
        }
        sVal[ty * 4 + i][tx] = best;
        sIdx[ty * 4 + i][tx] = bidx;
    }
    __syncthreads();

    if (tid < 64) {
        const int b = r0 + tid;
        float best = sVal[tid][0]; int bidx = sIdx[tid][0];
#pragma unroll
        for (int j = 1; j < 16; j++) {
            float v = sVal[tid][j]; int ix = sIdx[tid][j];
            if (v > best || (v == best && ix < bidx)) { best = v; bidx = ix; }
        }
        bool ended = (bidx == 0);
        int oldN = g_N[b];
        int newN = ended ? min(oldN, t) : oldN;
        if (ended) g_N[b] = newN;
        unsigned char an = (unsigned char)(g_alive[b] && !ended);
        g_alive[b] = an;
        int tk = an ? bidx : -1;
        g_tok[b] = tk;
        g_toks[t * Bn + b] = tk;
        sBtok[tid] = tk;
        if (t == Tn - 1) out[OUT_NOFF + b] = (float)newN;
    }
    __syncthreads();

    // dense one-hot write
    {
        const int row  = tid >> 2;
        const int cseg = (tid & 3) * 32;
        const int btok = sBtok[row];
        float* orow = out + ((size_t)(r0 + row) * Tn + t) * Vn + cseg;
#pragma unroll
        for (int q = 0; q < 8; q++) {
            const int c0 = cseg + q * 4;
            float4 v;
            v.x = (c0 + 0 == btok) ? 1.f : 0.f;
            v.y = (c0 + 1 == btok) ? 1.f : 0.f;
            v.z = (c0 + 2 == btok) ? 1.f : 0.f;
            v.w = (c0 + 3 == btok) ? 1.f : 0.f;
            *(float4*)(orow + q * 4) = v;
        }
    }
}

// ---------------- host ----------------
extern "C" void kernel_launch(void* const* d_in, const int* in_sizes, int n_in,
                              void* d_out, int out_size) {
    const float* x        = (const float*)d_in[0];
    const float* unif     = (const float*)d_in[2];
    const float* dec_Wd2e = (const float*)d_in[3];
    const float* dec_bd2e = (const float*)d_in[4];
    const float* dec_Wih  = (const float*)d_in[5];
    const float* dec_Whh  = (const float*)d_in[6];
    const float* dec_bih  = (const float*)d_in[7];
    const float* dec_bhh  = (const float*)d_in[8];
    const float* dec_We2d = (const float*)d_in[9];
    const float* dec_be2d = (const float*)d_in[10];
    const float* enc_Wd2e = (const float*)d_in[11];
    const float* enc_bd2e = (const float*)d_in[12];
    const float* enc_Wih  = (const float*)d_in[13];
    const float* enc_Whh  = (const float*)d_in[14];
    const float* enc_bih  = (const float*)d_in[15];
    const float* enc_bhh  = (const float*)d_in[16];
    float* out = (float*)d_out;

    void *p_h, *p_he, *p_Mdec, *p_cdec, *p_Menc, *p_cenc, *p_tok, *p_toks;
    cudaGetSymbolAddress(&p_h,    g_h);
    cudaGetSymbolAddress(&p_he,   g_he);
    cudaGetSymbolAddress(&p_Mdec, g_Mdec);
    cudaGetSymbolAddress(&p_cdec, g_cdec);
    cudaGetSymbolAddress(&p_Menc, g_Menc);
    cudaGetSymbolAddress(&p_cenc, g_cenc);
    cudaGetSymbolAddress(&p_tok,  g_tok);
    cudaGetSymbolAddress(&p_toks, g_toks);
    float* hb[2]  = { (float*)p_h,  (float*)p_h  + (size_t)Bn * En };
    float* heb[2] = { (float*)p_he, (float*)p_he + (size_t)Bn * En };
    float* Mdec = (float*)p_Mdec; float* cdec = (float*)p_cdec;
    float* Menc = (float*)p_Menc; float* cenc = (float*)p_cenc;
    int* tok = (int*)p_tok; int* toks = (int*)p_toks;

    const int NT = 256;
    const int gBE = (Bn * En + NT - 1) / NT;

    k_init<<<gBE, NT>>>(x);
    k_prep<<<dim3(Vn, G3 / 64), NT>>>(dec_Wih, dec_Wd2e, dec_bd2e, dec_bih, Mdec, cdec);
    k_prep<<<dim3(Vn, G3 / 64), NT>>>(enc_Wih, enc_Wd2e, enc_bd2e, enc_bih, Menc, cenc);

    dim3 gG1(Bn / 64, 4, 1);
    dim3 gG2(Bn / 64, 4, 2);
    dim3 gLog(Bn / 64);

    // t=0: decoder only
    k_gates2<<<gG1, NT>>>(hb[0], hb[1], dec_Whh, dec_bhh, Mdec, cdec, tok,
                          hb[0], hb[1], dec_Whh, dec_bhh, Mdec, cdec, tok);
    k_logits<<<gLog, NT>>>(hb[1], dec_We2d, dec_be2d, unif, out, 0);

    // encoder step 0 shortcut (hin is exactly zero): -> heb[1]
    k_enc0<<<gBE, NT>>>(heb[1], Menc, cenc, enc_bhh, toks + 0 * Bn);

    // t=1: decoder only
    k_gates2<<<gG1, NT>>>(hb[1], hb[0], dec_Whh, dec_bhh, Mdec, cdec, tok,
                          hb[1], hb[0], dec_Whh, dec_bhh, Mdec, cdec, tok);
    k_logits<<<gLog, NT>>>(hb[0], dec_We2d, dec_be2d, unif, out, 1);

    // t = 2..15: combined dec_gates(t) + enc_gates(t-1), then logits(t)
    for (int t = 2; t < Tn; t++) {
        k_gates2<<<gG2, NT>>>(hb[t & 1], hb[(t + 1) & 1], dec_Whh, dec_bhh, Mdec, cdec, tok,
                              heb[(t - 1) & 1], heb[t & 1], enc_Whh, enc_bhh, Menc, cenc,
                              toks + (t - 1) * Bn);
        k_logits<<<gLog, NT>>>(hb[(t + 1) & 1], dec_We2d, dec_be2d, unif, out, t);
    }

    // final encoder step 15: heb[1] -> out[reconst] directly
    k_gates2<<<gG1, NT>>>(heb[1], out + OUT_ROFF, enc_Whh, enc_bhh, Menc, cenc, toks + 15 * Bn,
                          heb[1], out + OUT_ROFF, enc_Whh, enc_bhh, Menc, cenc, toks + 15 * Bn);
}

// round 10
// speedup vs baseline: 1.1524x; 1.1524x over previous
#include <cuda_runtime.h>
#include <math.h>
#include <stdint.h>

#define Bn 16384
#define En 256
#define Vn 128
#define Tn 16
#define G3 768

#define OUT_UTT  ((size_t)Bn * Tn * Vn)
#define OUT_NOFF (OUT_UTT)
#define OUT_ROFF (OUT_UTT + Bn)

typedef unsigned long long ull;

// ---------------- packed f32x2 helpers ----------------
__device__ __forceinline__ ull pack2(float x, float y) {
    ull r; asm("mov.b64 %0, {%1, %2};" : "=l"(r) : "f"(x), "f"(y)); return r;
}
__device__ __forceinline__ void unpack2(ull v, float& x, float& y) {
    asm("mov.b64 {%0, %1}, %2;" : "=f"(x), "=f"(y) : "l"(v));
}
__device__ __forceinline__ void fma2(ull& c, ull a, ull b) {
    asm("fma.rn.f32x2 %0, %1, %2, %3;" : "=l"(c) : "l"(a), "l"(b), "l"(c));
}

// ---------------- device scratch ----------------
__device__ float g_h [2][Bn * En];
__device__ float g_he[2][Bn * En];
__device__ float g_Mdec[Vn * G3];
__device__ float g_cdec[G3];
__device__ float g_Menc[Vn * G3];
__device__ float g_cenc[G3];
__device__ int   g_tok [Bn];
__device__ int   g_toks[Tn * Bn];
__device__ int   g_N   [Bn];
__device__ int   g_ctr [256];          // per-64-row-group dec-gates completion counter
__device__ unsigned char g_alive[Bn];

// ---------------- init ----------------
__global__ void k_init(const float* __restrict__ x) {
    int i = blockIdx.x * blockDim.x + threadIdx.x;
    if (i < Bn * En) { g_h[0][i] = x[i]; }
    if (i < Bn)      { g_tok[i] = -1; g_alive[i] = 1; g_N[i] = Tn; }
    if (i < 256)     { g_ctr[i] = 0; }
}

// ---------------- k_prep: M = (Wih @ Wd2e)^T, cvec = Wih@bd2e + bih ----------------
__global__ void k_prep(const float* __restrict__ Wih, const float* __restrict__ Wd2e,
                       const float* __restrict__ bd2e, const float* __restrict__ bih,
                       float* __restrict__ M, float* __restrict__ cvec) {
    __shared__ float sw[En];
    __shared__ float sb[En];
    const int v  = blockIdx.x;
    const int j0 = blockIdx.y * 64;
    for (int e = threadIdx.x; e < En; e += 256) {
        sw[e] = Wd2e[e * Vn + v];
        if (v == 0) sb[e] = bd2e[e];
    }
    __syncthreads();
    const int warp = threadIdx.x >> 5, lane = threadIdx.x & 31;
#pragma unroll
    for (int jj = 0; jj < 8; jj++) {
        const int j = j0 + warp * 8 + jj;
        const float* wr = Wih + (size_t)j * En;
        float s = 0.f, c = 0.f;
#pragma unroll
        for (int e = lane; e < En; e += 32) {
            float w = wr[e];
            s += w * sw[e];
            if (v == 0) c += w * sb[e];
        }
#pragma unroll
        for (int o = 16; o; o >>= 1) {
            s += __shfl_xor_sync(0xffffffffu, s, o);
            if (v == 0) c += __shfl_xor_sync(0xffffffffu, c, o);
        }
        if (lane == 0) {
            M[v * G3 + j] = s;
            if (v == 0) cvec[j] = bih[j] + c;
        }
    }
}

__device__ __forceinline__ float sigm(float x) { return 1.f / (1.f + expf(-x)); }

// ---------------- k_enc0: encoder step 0 (hin == 0 exactly) ----------------
__global__ void k_enc0(float* __restrict__ hout,
                       const float* __restrict__ M, const float* __restrict__ cvec,
                       const float* __restrict__ bhh, const int* __restrict__ tokv) {
    int i = blockIdx.x * blockDim.x + threadIdx.x;
    if (i >= Bn * En) return;
    int b = i >> 8;
    int j = i & 255;
    int tk = tokv[b];
    float mr = 0.f, mz = 0.f, mn = 0.f;
    if (tk >= 0) {
        const float* Mr = M + (size_t)tk * G3;
        mr = Mr[j]; mz = Mr[256 + j]; mn = Mr[512 + j];
    }
    float ir = mr + cvec[j],        hr = 0.f + bhh[j];
    float iz = mz + cvec[256 + j],  hz = 0.f + bhh[256 + j];
    float in_= mn + cvec[512 + j],  hn = 0.f + bhh[512 + j];
    float r = sigm(ir + hr);
    float z = sigm(iz + hz);
    float n = tanhf(in_ + r * hn);
    hout[i] = (1.f - z) * n + z * 0.f;
}

// ---------------- gates body (R8 inner loop, dynamic smem) ----------------
__device__ __forceinline__ void gates_body(char* smp, int r0, int j0,
    const float* __restrict__ hin, float* __restrict__ hout,
    const float* __restrict__ Whh, const float* __restrict__ bhh,
    const float* __restrict__ M, const float* __restrict__ cvec,
    const int* __restrict__ tok, int ctr_idx)
{
    float (*As)[16][68]  = (float(*)[16][68])(smp);
    float (*Ws)[16][196] = (float(*)[16][196])(smp + 8704);
    const int t  = threadIdx.x;
    const int ty = t >> 4, tx = t & 15;

    const int lr  = t >> 2;
    const int lkq = (t & 3) * 4;
    const float* Ag  = hin + (size_t)(r0 + lr) * En + lkq;
    const float* Wg0 = Whh + (size_t)(0 * En + j0 + lr) * En + lkq;
    const float* Wg1 = Whh + (size_t)(1 * En + j0 + lr) * En + lkq;
    const float* Wg2 = Whh + (size_t)(2 * En + j0 + lr) * En + lkq;

    float4 av = *(const float4*)Ag;
    float4 w0 = *(const float4*)Wg0;
    float4 w1 = *(const float4*)Wg1;
    float4 w2 = *(const float4*)Wg2;

    ull acc2[3][4][2];
#pragma unroll
    for (int g = 0; g < 3; g++)
#pragma unroll
        for (int i = 0; i < 4; i++) { acc2[g][i][0] = 0ull; acc2[g][i][1] = 0ull; }

    As[0][lkq+0][lr] = av.x; As[0][lkq+1][lr] = av.y; As[0][lkq+2][lr] = av.z; As[0][lkq+3][lr] = av.w;
    Ws[0][lkq+0][lr      ] = w0.x; Ws[0][lkq+1][lr      ] = w0.y; Ws[0][lkq+2][lr      ] = w0.z; Ws[0][lkq+3][lr      ] = w0.w;
    Ws[0][lkq+0][64  + lr] = w1.x; Ws[0][lkq+1][64  + lr] = w1.y; Ws[0][lkq+2][64  + lr] = w1.z; Ws[0][lkq+3][64  + lr] = w1.w;
    Ws[0][lkq+0][128 + lr] = w2.x; Ws[0][lkq+1][128 + lr] = w2.y; Ws[0][lkq+2][128 + lr] = w2.z; Ws[0][lkq+3][128 + lr] = w2.w;
    __syncthreads();

    for (int kt = 0; kt < 16; kt++) {
        const int buf = kt & 1;
        if (kt < 15) {
            av = *(const float4*)(Ag  + (kt + 1) * 16);
            w0 = *(const float4*)(Wg0 + (kt + 1) * 16);
            w1 = *(const float4*)(Wg1 + (kt + 1) * 16);
            w2 = *(const float4*)(Wg2 + (kt + 1) * 16);
        }
#pragma unroll
        for (int k = 0; k < 16; k++) {
            float4 af = *(const float4*)&As[buf][k][ty * 4];
            ull ap[4];
            ap[0] = pack2(af.x, af.x); ap[1] = pack2(af.y, af.y);
            ap[2] = pack2(af.z, af.z); ap[3] = pack2(af.w, af.w);
            ull bp[3][2];
#pragma unroll
            for (int g = 0; g < 3; g++) {
                bp[g][0] = *(const ull*)&Ws[buf][k][g * 64 + tx * 4];
                bp[g][1] = *(const ull*)&Ws[buf][k][g * 64 + tx * 4 + 2];
            }
#pragma unroll
            for (int i = 0; i < 4; i++)
#pragma unroll
                for (int g = 0; g < 3; g++) {
                    fma2(acc2[g][i][0], ap[i], bp[g][0]);
                    fma2(acc2[g][i][1], ap[i], bp[g][1]);
                }
        }
        if (kt < 15) {
            const int nb = buf ^ 1;
            As[nb][lkq+0][lr] = av.x; As[nb][lkq+1][lr] = av.y; As[nb][lkq+2][lr] = av.z; As[nb][lkq+3][lr] = av.w;
            Ws[nb][lkq+0][lr      ] = w0.x; Ws[nb][lkq+1][lr      ] = w0.y; Ws[nb][lkq+2][lr      ] = w0.z; Ws[nb][lkq+3][lr      ] = w0.w;
            Ws[nb][lkq+0][64  + lr] = w1.x; Ws[nb][lkq+1][64  + lr] = w1.y; Ws[nb][lkq+2][64  + lr] = w1.z; Ws[nb][lkq+3][64  + lr] = w1.w;
            Ws[nb][lkq+0][128 + lr] = w2.x; Ws[nb][lkq+1][128 + lr] = w2.y; Ws[nb][lkq+2][128 + lr] = w2.z; Ws[nb][lkq+3][128 + lr] = w2.w;
            __syncthreads();
        }
    }

    float cv[3][4], bh[3][4];
#pragma unroll
    for (int g = 0; g < 3; g++) {
        float4 cf = *(const float4*)(cvec + g * En + j0 + tx * 4);
        cv[g][0]=cf.x; cv[g][1]=cf.y; cv[g][2]=cf.z; cv[g][3]=cf.w;
        float4 bf = *(const float4*)(bhh + g * En + j0 + tx * 4);
        bh[g][0]=bf.x; bh[g][1]=bf.y; bh[g][2]=bf.z; bh[g][3]=bf.w;
    }
#pragma unroll
    for (int i = 0; i < 4; i++) {
        const int rr = r0 + ty * 4 + i;
        const int tk = tok[rr];
        float m[3][4];
        if (tk >= 0) {
            const float* Mr = M + (size_t)tk * G3 + j0 + tx * 4;
#pragma unroll
            for (int g = 0; g < 3; g++) {
                float4 mf = *(const float4*)(Mr + g * En);
                m[g][0]=mf.x; m[g][1]=mf.y; m[g][2]=mf.z; m[g][3]=mf.w;
            }
        } else {
#pragma unroll
            for (int g = 0; g < 3; g++)
#pragma unroll
                for (int c = 0; c < 4; c++) m[g][c] = 0.f;
        }
        float acc[3][4];
#pragma unroll
        for (int g = 0; g < 3; g++) {
            unpack2(acc2[g][i][0], acc[g][0], acc[g][1]);
            unpack2(acc2[g][i][1], acc[g][2], acc[g][3]);
        }
        float4 hof = *(const float4*)(hin + (size_t)rr * En + j0 + tx * 4);
        float hold[4] = {hof.x, hof.y, hof.z, hof.w};
        float hnew[4];
#pragma unroll
        for (int c = 0; c < 4; c++) {
            float ir = m[0][c] + cv[0][c], hr = acc[0][c] + bh[0][c];
            float iz = m[1][c] + cv[1][c], hz = acc[1][c] + bh[1][c];
            float in_= m[2][c] + cv[2][c], hn = acc[2][c] + bh[2][c];
            float r = sigm(ir + hr);
            float z = sigm(iz + hz);
            float n = tanhf(in_ + r * hn);
            hnew[c] = (1.f - z) * n + z * hold[c];
        }
        *(float4*)(hout + (size_t)rr * En + j0 + tx * 4) = make_float4(hnew[0], hnew[1], hnew[2], hnew[3]);
    }

    if (ctr_idx >= 0) {
        __threadfence();
        __syncthreads();
        if (threadIdx.x == 0) atomicAdd(&g_ctr[ctr_idx], 1);
    }
}

// ---------------- logits body (R8, dynamic smem, spin-release) ----------------
__device__ __forceinline__ void logits_body(char* smp, int rg,
    const float* __restrict__ hin, const float* __restrict__ We2d,
    const float* __restrict__ be2d, const float* __restrict__ unif,
    float* __restrict__ out, int t, int expected)
{
    // wait until this row group's 4 dec-gates blocks have completed
    if (threadIdx.x == 0) {
        while (atomicAdd(&g_ctr[rg], 0) < expected) { }
    }
    __syncthreads();
    __threadfence();

    float (*As)[16][68]  = (float(*)[16][68])(smp);
    float (*Ws)[16][132] = (float(*)[16][132])(smp + 8704);
    float (*sVal)[17]    = (float(*)[17])(smp + 25600);
    int   (*sIdx)[17]    = (int(*)[17])(smp + 29952);
    int*  sBtok          = (int*)(smp + 34304);

    const int tid = threadIdx.x;
    const int r0 = rg * 64;
    const int ty = tid >> 4, tx = tid & 15;

    const int lr  = tid >> 2;
    const int lkq = (tid & 3) * 4;
    const float* Ag = hin + (size_t)(r0 + lr) * En + lkq;
    const int wn  = tid >> 1;
    const int wkq = (tid & 1) * 8;
    const float* Wg = We2d + (size_t)wn * En + wkq;

    float4 av = *(const float4*)Ag;
    float4 w0 = *(const float4*)Wg;
    float4 w1 = *(const float4*)(Wg + 4);

    ull acc2[4][4];
#pragma unroll
    for (int i = 0; i < 4; i++)
#pragma unroll
        for (int p = 0; p < 4; p++) acc2[i][p] = 0ull;

    As[0][lkq+0][lr] = av.x; As[0][lkq+1][lr] = av.y; As[0][lkq+2][lr] = av.z; As[0][lkq+3][lr] = av.w;
    Ws[0][wkq+0][wn] = w0.x; Ws[0][wkq+1][wn] = w0.y; Ws[0][wkq+2][wn] = w0.z; Ws[0][wkq+3][wn] = w0.w;
    Ws[0][wkq+4][wn] = w1.x; Ws[0][wkq+5][wn] = w1.y; Ws[0][wkq+6][wn] = w1.z; Ws[0][wkq+7][wn] = w1.w;
    __syncthreads();

    for (int kt = 0; kt < 16; kt++) {
        const int buf = kt & 1;
        if (kt < 15) {
            av = *(const float4*)(Ag + (kt + 1) * 16);
            w0 = *(const float4*)(Wg + (kt + 1) * 16);
            w1 = *(const float4*)(Wg + (kt + 1) * 16 + 4);
        }
#pragma unroll
        for (int k = 0; k < 16; k++) {
            float4 af = *(const float4*)&As[buf][k][ty * 4];
            ull ap[4];
            ap[0] = pack2(af.x, af.x); ap[1] = pack2(af.y, af.y);
            ap[2] = pack2(af.z, af.z); ap[3] = pack2(af.w, af.w);
            ull bp[4];
            bp[0] = *(const ull*)&Ws[buf][k][     tx * 4];
            bp[1] = *(const ull*)&Ws[buf][k][     tx * 4 + 2];
            bp[2] = *(const ull*)&Ws[buf][k][64 + tx * 4];
            bp[3] = *(const ull*)&Ws[buf][k][64 + tx * 4 + 2];
#pragma unroll
            for (int i = 0; i < 4; i++)
#pragma unroll
                for (int p = 0; p < 4; p++) fma2(acc2[i][p], ap[i], bp[p]);
        }
        if (kt < 15) {
            const int nb = buf ^ 1;
            As[nb][lkq+0][lr] = av.x; As[nb][lkq+1][lr] = av.y; As[nb][lkq+2][lr] = av.z; As[nb][lkq+3][lr] = av.w;
            Ws[nb][wkq+0][wn] = w0.x; Ws[nb][wkq+1][wn] = w0.y; Ws[nb][wkq+2][wn] = w0.z; Ws[nb][wkq+3][wn] = w0.w;
            Ws[nb][wkq+4][wn] = w1.x; Ws[nb][wkq+5][wn] = w1.y; Ws[nb][wkq+6][wn] = w1.z; Ws[nb][wkq+7][wn] = w1.w;
            __syncthreads();
        }
    }

    float be[8];
    {
        float4 b0 = *(const float4*)(be2d +      tx * 4);
        float4 b1 = *(const float4*)(be2d + 64 + tx * 4);
        be[0]=b0.x; be[1]=b0.y; be[2]=b0.z; be[3]=b0.w;
        be[4]=b1.x; be[5]=b1.y; be[6]=b1.z; be[7]=b1.w;
    }
#pragma unroll
    for (int i = 0; i < 4; i++) {
        const int rr = r0 + ty * 4 + i;
        const float* urow = unif + ((size_t)t * Bn + rr) * Vn;
        float acc[8];
        unpack2(acc2[i][0], acc[0], acc[1]);
        unpack2(acc2[i][1], acc[2], acc[3]);
        unpack2(acc2[i][2], acc[4], acc[5]);
        unpack2(acc2[i][3], acc[6], acc[7]);
        float best = -INFINITY; int bidx = Vn;
#pragma unroll
        for (int c = 0; c < 8; c++) {
            const int col = (c < 4) ? (tx * 4 + c) : (64 + tx * 4 + (c - 4));
            float u = urow[col];
            float g = -logf(-logf(u + 1e-10f) + 1e-10f);
            float v = acc[c] + be[c] + g;
            if (v > best || (v == best && col < bidx)) { best = v; bidx = col; }
        }
        sVal[ty * 4 + i][tx] = best;
        sIdx[ty * 4 + i][tx] = bidx;
    }
    __syncthreads();

    if (tid < 64) {
        const int b = r0 + tid;
        float best = sVal[tid][0]; int bidx = sIdx[tid][0];
#pragma unroll
        for (int j = 1; j < 16; j++) {
            float v = sVal[tid][j]; int ix = sIdx[tid][j];
            if (v > best || (v == best && ix < bidx)) { best = v; bidx = ix; }
        }
        bool ended = (bidx == 0);
        int oldN = g_N[b];
        int newN = ended ? min(oldN, t) : oldN;
        if (ended) g_N[b] = newN;
        unsigned char an = (unsigned char)(g_alive[b] && !ended);
        g_alive[b] = an;
        int tk = an ? bidx : -1;
        g_tok[b] = tk;
        g_toks[t * Bn + b] = tk;
        sBtok[tid] = tk;
        if (t == Tn - 1) out[OUT_NOFF + b] = (float)newN;
    }
    __syncthreads();

    {
        const int row  = tid >> 2;
        const int cseg = (tid & 3) * 32;
        const int btok = sBtok[row];
        float* orow = out + ((size_t)(r0 + row) * Tn + t) * Vn + cseg;
#pragma unroll
        for (int q = 0; q < 8; q++) {
            const int c0 = cseg + q * 4;
            float4 v;
            v.x = (c0 + 0 == btok) ? 1.f : 0.f;
            v.y = (c0 + 1 == btok) ? 1.f : 0.f;
            v.z = (c0 + 2 == btok) ? 1.f : 0.f;
            v.w = (c0 + 3 == btok) ? 1.f : 0.f;
            *(float4*)(orow + q * 4) = v;
        }
    }
}

// ---------------- fused per-step kernel ----------------
#define STEP_SMEM 34816

__global__ __launch_bounds__(256, 2) void k_step(
    const float* dhin, float* dhout, const float* dWhh, const float* dbhh,
    const float* dM, const float* dcv,
    const float* ehin, float* ehout, const float* eWhh, const float* ebhh,
    const float* eM, const float* ecv, const int* etok, int enc_blocks,
    const float* We2d, const float* be2d, const float* unif, float* out,
    int t, int expected)
{
    extern __shared__ char smp[];
    const int bx = blockIdx.x;
    if (bx < 1024) {
        gates_body(smp, (bx & 255) * 64, (bx >> 8) * 64,
                   dhin, dhout, dWhh, dbhh, dM, dcv, g_tok, bx & 255);
    } else if (bx < 1024 + enc_blocks) {
        const int i = bx - 1024;
        gates_body(smp, (i & 255) * 64, (i >> 8) * 64,
                   ehin, ehout, eWhh, ebhh, eM, ecv, etok, -1);
    } else {
        logits_body(smp, bx - 1024 - enc_blocks,
                    dhout, We2d, be2d, unif, out, t, expected);
    }
}

// ---------------- standalone gates (tail encoder step) ----------------
__global__ __launch_bounds__(256, 2) void k_gates_tail(
    const float* hin, float* hout, const float* Whh, const float* bhh,
    const float* M, const float* cvec, const int* tok)
{
    extern __shared__ char smp[];
    gates_body(smp, blockIdx.x * 64, blockIdx.y * 64,
               hin, hout, Whh, bhh, M, cvec, tok, -1);
}

// ---------------- host ----------------
extern "C" void kernel_launch(void* const* d_in, const int* in_sizes, int n_in,
                              void* d_out, int out_size) {
    const float* x        = (const float*)d_in[0];
    const float* unif     = (const float*)d_in[2];
    const float* dec_Wd2e = (const float*)d_in[3];
    const float* dec_bd2e = (const float*)d_in[4];
    const float* dec_Wih  = (const float*)d_in[5];
    const float* dec_Whh  = (const float*)d_in[6];
    const float* dec_bih  = (const float*)d_in[7];
    const float* dec_bhh  = (const float*)d_in[8];
    const float* dec_We2d = (const float*)d_in[9];
    const float* dec_be2d = (const float*)d_in[10];
    const float* enc_Wd2e = (const float*)d_in[11];
    const float* enc_bd2e = (const float*)d_in[12];
    const float* enc_Wih  = (const float*)d_in[13];
    const float* enc_Whh  = (const float*)d_in[14];
    const float* enc_bih  = (const float*)d_in[15];
    const float* enc_bhh  = (const float*)d_in[16];
    float* out = (float*)d_out;

    void *p_h, *p_he, *p_Mdec, *p_cdec, *p_Menc, *p_cenc, *p_tok, *p_toks;
    cudaGetSymbolAddress(&p_h,    g_h);
    cudaGetSymbolAddress(&p_he,   g_he);
    cudaGetSymbolAddress(&p_Mdec, g_Mdec);
    cudaGetSymbolAddress(&p_cdec, g_cdec);
    cudaGetSymbolAddress(&p_Menc, g_Menc);
    cudaGetSymbolAddress(&p_cenc, g_cenc);
    cudaGetSymbolAddress(&p_tok,  g_tok);
    cudaGetSymbolAddress(&p_toks, g_toks);
    float* hb[2]  = { (float*)p_h,  (float*)p_h  + (size_t)Bn * En };
    float* heb[2] = { (float*)p_he, (float*)p_he + (size_t)Bn * En };
    float* Mdec = (float*)p_Mdec; float* cdec = (float*)p_cdec;
    float* Menc = (float*)p_Menc; float* cenc = (float*)p_cenc;
    int* tok = (int*)p_tok; int* toks = (int*)p_toks;
    (void)tok;

    const int NT = 256;
    const int gBE = (Bn * En + NT - 1) / NT;

    k_init<<<gBE, NT>>>(x);
    k_prep<<<dim3(Vn, G3 / 64), NT>>>(dec_Wih, dec_Wd2e, dec_bd2e, dec_bih, Mdec, cdec);
    k_prep<<<dim3(Vn, G3 / 64), NT>>>(enc_Wih, enc_Wd2e, enc_bd2e, enc_bih, Menc, cenc);

    // t=0: dec gates + logits fused (no enc work)
    k_step<<<1280, NT, STEP_SMEM>>>(hb[0], hb[1], dec_Whh, dec_bhh, Mdec, cdec,
                                    heb[0], heb[1], enc_Whh, enc_bhh, Menc, cenc, toks, 0,
                                    dec_We2d, dec_be2d, unif, out, 0, 4);
    // encoder step 0 shortcut (hin exactly zero)
    k_enc0<<<gBE, NT>>>(heb[1], Menc, cenc, enc_bhh, toks + 0 * Bn);

    // t=1: dec gates + logits fused
    k_step<<<1280, NT, STEP_SMEM>>>(hb[1], hb[0], dec_Whh, dec_bhh, Mdec, cdec,
                                    heb[0], heb[1], enc_Whh, enc_bhh, Menc, cenc, toks, 0,
                                    dec_We2d, dec_be2d, unif, out, 1, 8);

    // t=2..15: dec gates(t) + enc gates(t-1) + logits(t) in ONE launch
    for (int t = 2; t < Tn; t++) {
        k_step<<<2304, NT, STEP_SMEM>>>(hb[t & 1], hb[(t + 1) & 1], dec_Whh, dec_bhh, Mdec, cdec,
                                        heb[(t - 1) & 1], heb[t & 1], enc_Whh, enc_bhh, Menc, cenc,
                                        toks + (t - 1) * Bn, 1024,
                                        dec_We2d, dec_be2d, unif, out, t, 4 * (t + 1));
    }

    // tail: encoder step 15 -> reconst region of out
    k_gates_tail<<<dim3(Bn / 64, 4), NT, STEP_SMEM>>>(heb[1], out + OUT_ROFF,
                                                      enc_Whh, enc_bhh, Menc, cenc,
                                                      toks + 15 * Bn);
}